// round 9
// baseline (speedup 1.0000x reference)
#include <cuda_runtime.h>
#include <cuda_fp16.h>
#include <cstdint>

// ============================================================================
// ViTMAE attention block: B=16, S=1024, HID=1024, HEADS=16, D=64, fp32 I/O.
// fp16 tensor cores (mma.m16n8k16, fp32 accum) + ldmatrix everywhere.
//   pre: x -> fp16 copy;  W* -> fp16 TRANSPOSED copies (one fused launch)
//   q/k/v = x@W + b  (3-stage cp.async fp16 MMA, BN=256, warp tile 64x64)
//   ctx = softmax(q k^T) v  (fp16 flash attention, Bc=64, fp32 softmax)
//   out = ctx@Wd + bd  (fp32 output)
// ============================================================================

#define BATCH   16
#define SEQ     1024
#define HID     1024
#define HEADS   16
#define HDIM    64
#define MROWS   (BATCH * SEQ)   // 16384

__device__ __half g_q[(size_t)BATCH * HEADS * SEQ * HDIM];
__device__ __half g_k[(size_t)BATCH * HEADS * SEQ * HDIM];
__device__ __half g_v[(size_t)BATCH * HEADS * SEQ * HDIM];
__device__ __half g_ctx[(size_t)MROWS * HID];
__device__ __half g_hs[(size_t)MROWS * HID];
__device__ __half g_wq[(size_t)HID * HID];   // transposed: [n][k]
__device__ __half g_wk[(size_t)HID * HID];
__device__ __half g_wv[(size_t)HID * HID];
__device__ __half g_wd[(size_t)HID * HID];

__device__ __forceinline__ void cp16(void* smem, const void* gmem) {
    uint32_t s = (uint32_t)__cvta_generic_to_shared(smem);
    asm volatile("cp.async.cg.shared.global [%0], [%1], 16;" :: "r"(s), "l"(gmem));
}
#define CP_COMMIT() asm volatile("cp.async.commit_group;")
#define CP_WAIT(n)  asm volatile("cp.async.wait_group %0;" :: "n"(n))

__device__ __forceinline__ uint32_t smem_u32(const void* p) {
    return (uint32_t)__cvta_generic_to_shared(p);
}
__device__ __forceinline__ void ldsm4(uint32_t* r, uint32_t addr) {
    asm volatile("ldmatrix.sync.aligned.m8n8.x4.shared.b16 {%0,%1,%2,%3}, [%4];"
        : "=r"(r[0]), "=r"(r[1]), "=r"(r[2]), "=r"(r[3]) : "r"(addr));
}
__device__ __forceinline__ void ldsm2t(uint32_t* r, uint32_t addr) {
    asm volatile("ldmatrix.sync.aligned.m8n8.x2.trans.shared.b16 {%0,%1}, [%2];"
        : "=r"(r[0]), "=r"(r[1]) : "r"(addr));
}

#define MMA_F16(d, a, b)                                                      \
    asm volatile(                                                             \
        "mma.sync.aligned.m16n8k16.row.col.f32.f16.f16.f32 "                  \
        "{%0,%1,%2,%3}, {%4,%5,%6,%7}, {%8,%9}, {%0,%1,%2,%3};"               \
        : "+f"(d[0]), "+f"(d[1]), "+f"(d[2]), "+f"(d[3])                      \
        : "r"(a[0]), "r"(a[1]), "r"(a[2]), "r"(a[3]), "r"(b[0]), "r"(b[1]))

// ----------------------------------------------------------------------------
// pre-passes: fp32 -> fp16
// ----------------------------------------------------------------------------
__global__ __launch_bounds__(256) void round_copy_hs(const float* __restrict__ src, int n4)
{
    int i = blockIdx.x * blockDim.x + threadIdx.x;
    if (i < n4) {
        float4 v = ((const float4*)src)[i];
        ((__half2*)g_hs)[2 * i + 0] = __floats2half2_rn(v.x, v.y);
        ((__half2*)g_hs)[2 * i + 1] = __floats2half2_rn(v.z, v.w);
    }
}

// all four transposed fp16 weight copies in ONE launch (blockIdx.z selects)
__global__ __launch_bounds__(256) void wt_copy_all(
    const float* __restrict__ s0, const float* __restrict__ s1,
    const float* __restrict__ s2, const float* __restrict__ s3)
{
    __shared__ float tile[32][33];
    int which = blockIdx.z;
    const float* src = which == 0 ? s0 : which == 1 ? s1 : which == 2 ? s2 : s3;
    __half* dst = which == 0 ? g_wq : which == 1 ? g_wk :
                  which == 2 ? g_wv : g_wd;
    int tx = threadIdx.x & 31, ty = threadIdx.x >> 5;   // 32 x 8
    int x0 = blockIdx.x * 32, y0 = blockIdx.y * 32;
#pragma unroll
    for (int i = 0; i < 32; i += 8)
        tile[ty + i][tx] = src[(size_t)(y0 + ty + i) * HID + x0 + tx];
    __syncthreads();
#pragma unroll
    for (int i = 0; i < 32; i += 8)
        dst[(size_t)(x0 + ty + i) * HID + y0 + tx] = __float2half_rn(tile[tx][ty + i]);
}

// ----------------------------------------------------------------------------
// fp16 GEMM, 3-stage cp.async + ldmatrix. BM=128, BN=256, BK=32,
// 256 threads (8 warps 2x4), warp tile 64x64 (4x8 m16n8k16 per k16-step).
// MODE 0: A=g_ctx, Wt=g_wd, out fp32 row-major (+bias).
// MODE 1: A=g_hs, Wt per which, out = h((acc+bias)*osc) scattered [B,H,S,D].
// smem: 3 stages x (A 128x40 + B 256x40) halves = 92160 B.
// ----------------------------------------------------------------------------
#define GEMM_SMEM (3 * (128 * 40 + 256 * 40) * 2)

template <int MODE>
__global__ __launch_bounds__(256) void h_gemm(
    const float* __restrict__ bias, float* __restrict__ outArg, int which,
    float osc)
{
    extern __shared__ __half smg[];
#define AS(s, r, c) smg[(s) * 15360 + (r) * 40 + (c)]
#define BS(s, r, c) smg[(s) * 15360 + 5120 + (r) * 40 + (c)]

    const __half* __restrict__ A  = (MODE == 0) ? g_ctx : g_hs;
    const __half* __restrict__ Wt = which == 0 ? g_wq : which == 1 ? g_wk :
                                    which == 2 ? g_wv : g_wd;
    float* outF = outArg;
    __half* outH = (which == 0) ? g_q : (which == 1) ? g_k : g_v;

    const int tid = threadIdx.x;
    const int lane = tid & 31, warp = tid >> 5;
    const int wm = warp >> 2, wn = warp & 3;
    const int g = lane >> 2, t = lane & 3;
    const int row0 = blockIdx.y * 128;
    const int col0 = blockIdx.x * 256;

    float acc[4][8][4];
#pragma unroll
    for (int mt = 0; mt < 4; mt++)
#pragma unroll
        for (int nt = 0; nt < 8; nt++)
#pragma unroll
            for (int i = 0; i < 4; i++) acc[mt][nt][i] = 0.f;

    auto stage = [&](int s, int k0) {
        // BK=32 -> 4 chunks of 8 halves per row.
        // A: 128 rows x 4 = 512 chunks; B: 256 rows x 4 = 1024 chunks.
#pragma unroll
        for (int j = 0; j < 2; j++) {
            int cid = tid + j * 256;
            int r = cid >> 2, q = cid & 3;
            cp16(&AS(s, r, q * 8), &A[(size_t)(row0 + r) * HID + k0 + q * 8]);
        }
#pragma unroll
        for (int j = 0; j < 4; j++) {
            int cid = tid + j * 256;
            int r = cid >> 2, q = cid & 3;
            cp16(&BS(s, r, q * 8), &Wt[(size_t)(col0 + r) * HID + k0 + q * 8]);
        }
    };

    const int NIT = HID / 32;   // 32
    stage(0, 0);  CP_COMMIT();
    stage(1, 32); CP_COMMIT();

    for (int it = 0; it < NIT; it++) {
        if (it + 1 < NIT) { CP_WAIT(1); } else { CP_WAIT(0); }
        __syncthreads();
        if (it + 2 < NIT) { stage((it + 2) % 3, (it + 2) * 32); CP_COMMIT(); }

        const int s = it % 3;
#pragma unroll
        for (int ks = 0; ks < 32; ks += 16) {
            uint32_t a[4][4], b[4][4];
#pragma unroll
            for (int mt = 0; mt < 4; mt++)
                ldsm4(a[mt], smem_u32(&AS(s, wm * 64 + mt * 16 + (lane & 15),
                                          ks + 8 * (lane >> 4))));
#pragma unroll
            for (int nt16 = 0; nt16 < 4; nt16++)
                ldsm4(b[nt16], smem_u32(&BS(s, wn * 64 + nt16 * 16 + (lane & 15),
                                            ks + 8 * (lane >> 4))));
#pragma unroll
            for (int mt = 0; mt < 4; mt++)
#pragma unroll
                for (int nt16 = 0; nt16 < 4; nt16++) {
                    uint32_t b0[2] = { b[nt16][0], b[nt16][2] };
                    uint32_t b1[2] = { b[nt16][1], b[nt16][3] };
                    MMA_F16(acc[mt][nt16 * 2 + 0], a[mt], b0);
                    MMA_F16(acc[mt][nt16 * 2 + 1], a[mt], b1);
                }
        }
    }

#pragma unroll
    for (int mt = 0; mt < 4; mt++) {
#pragma unroll
        for (int nt = 0; nt < 8; nt++) {
            int n = col0 + wn * 64 + nt * 8 + 2 * t;
            float b0 = bias[n], b1 = bias[n + 1];
#pragma unroll
            for (int hf = 0; hf < 2; hf++) {
                int m = row0 + wm * 64 + mt * 16 + g + hf * 8;
                float vx = acc[mt][nt][hf * 2 + 0] + b0;
                float vy = acc[mt][nt][hf * 2 + 1] + b1;
                if (MODE == 0) {
                    *(float2*)&outF[(size_t)m * HID + n] = make_float2(vx, vy);
                } else {
                    __half2 hv = __floats2half2_rn(vx * osc, vy * osc);
                    int bb = m >> 10, sq = m & 1023;
                    int h = n >> 6, d = n & 63;
                    *(__half2*)&outH[(((size_t)bb * HEADS + h) * SEQ + sq) * HDIM + d] = hv;
                }
            }
        }
    }
#undef AS
#undef BS
}

// ----------------------------------------------------------------------------
// fp16 flash attention, Bc=64, 3-stage cp.async K/V pipeline + ldmatrix.
// Grid (8 qtiles, 16 h, 16 b), 256 threads (8 warps, 16 q-rows each).
// Br=128, Bc=64, D=64. q pre-scaled by 0.125*log2e. fp32 softmax/accum.
// smem halves: Q 128x72 | K 3x64x72 | V 3x64x72 | P 128x72 = 92160 B.
// ----------------------------------------------------------------------------
#define ATTN_SMEM ((128 * 72 + 3 * 64 * 72 + 3 * 64 * 72 + 128 * 72) * 2)

__global__ __launch_bounds__(256) void attn_kernel()
{
    extern __shared__ __half sma[];
#define QS(r, c)    sma[(r) * 72 + (c)]
#define KS(s, r, c) sma[9216  + (s) * 4608 + (r) * 72 + (c)]
#define VS(s, r, c) sma[23040 + (s) * 4608 + (r) * 72 + (c)]
#define PS(r, c)    sma[36864 + (r) * 72 + (c)]

    const int tid = threadIdx.x;
    const int lane = tid & 31, warp = tid >> 5;
    const int g = lane >> 2, t = lane & 3;
    const int w16 = warp * 16;
    const int qt = blockIdx.x, h = blockIdx.y, b = blockIdx.z;
    const size_t bh = (size_t)b * HEADS + h;
    const __half* __restrict__ qb = g_q + (bh * SEQ + qt * 128) * HDIM;
    const __half* __restrict__ kb = g_k + bh * SEQ * HDIM;
    const __half* __restrict__ vb = g_v + bh * SEQ * HDIM;

    // D=64 -> 8 chunks of 8 halves per row.
    auto stageKV = [&](int s, int kc) {
        // 64 rows x 8 chunks = 512 chunks each for K and V; 2 per thread.
#pragma unroll
        for (int j = 0; j < 2; j++) {
            int i = tid + j * 256;
            int r = i >> 3, c = (i & 7) * 8;
            cp16(&KS(s, r, c), &kb[(size_t)(kc + r) * HDIM + c]);
            cp16(&VS(s, r, c), &vb[(size_t)(kc + r) * HDIM + c]);
        }
    };

    // Q: 128 rows x 8 chunks = 1024 chunks.
#pragma unroll
    for (int j = 0; j < 4; j++) {
        int i = tid + j * 256;
        int r = i >> 3, c = (i & 7) * 8;
        cp16(&QS(r, c), &qb[(size_t)r * HDIM + c]);
    }
    stageKV(0, 0);  CP_COMMIT();
    stageKV(1, 64); CP_COMMIT();

    float m0 = -1e30f, m1 = -1e30f, l0 = 0.f, l1 = 0.f;
    float o[8][4];
#pragma unroll
    for (int d = 0; d < 8; d++)
#pragma unroll
        for (int i = 0; i < 4; i++) o[d][i] = 0.f;

    const int NKV = SEQ / 64;   // 16
    for (int it = 0; it < NKV; it++) {
        if (it + 1 < NKV) { CP_WAIT(1); } else { CP_WAIT(0); }
        __syncthreads();
        if (it + 2 < NKV) { stageKV((it + 2) % 3, (it + 2) * 64); CP_COMMIT(); }

        const int s = it % 3;

        // S[16x64] = Q_warp @ K^T
        float sc[8][4];
#pragma unroll
        for (int nt = 0; nt < 8; nt++)
#pragma unroll
            for (int i = 0; i < 4; i++) sc[nt][i] = 0.f;

#pragma unroll
        for (int ks = 0; ks < 64; ks += 16) {
            uint32_t a[4], kf[4][4];
            ldsm4(a, smem_u32(&QS(w16 + (lane & 15), ks + 8 * (lane >> 4))));
#pragma unroll
            for (int nt16 = 0; nt16 < 4; nt16++)
                ldsm4(kf[nt16], smem_u32(&KS(s, nt16 * 16 + (lane & 15),
                                             ks + 8 * (lane >> 4))));
#pragma unroll
            for (int nt16 = 0; nt16 < 4; nt16++) {
                uint32_t b0[2] = { kf[nt16][0], kf[nt16][2] };
                uint32_t b1[2] = { kf[nt16][1], kf[nt16][3] };
                MMA_F16(sc[nt16 * 2 + 0], a, b0);
                MMA_F16(sc[nt16 * 2 + 1], a, b1);
            }
        }

        // online softmax (rows g, g+8)
        float mx0 = -1e30f, mx1 = -1e30f;
#pragma unroll
        for (int nt = 0; nt < 8; nt++) {
            mx0 = fmaxf(mx0, fmaxf(sc[nt][0], sc[nt][1]));
            mx1 = fmaxf(mx1, fmaxf(sc[nt][2], sc[nt][3]));
        }
        mx0 = fmaxf(mx0, __shfl_xor_sync(0xffffffffu, mx0, 1));
        mx0 = fmaxf(mx0, __shfl_xor_sync(0xffffffffu, mx0, 2));
        mx1 = fmaxf(mx1, __shfl_xor_sync(0xffffffffu, mx1, 1));
        mx1 = fmaxf(mx1, __shfl_xor_sync(0xffffffffu, mx1, 2));

        float mn0 = fmaxf(m0, mx0), mn1 = fmaxf(m1, mx1);
        float corr0 = exp2f(m0 - mn0), corr1 = exp2f(m1 - mn1);
        m0 = mn0; m1 = mn1;

        float sum0 = 0.f, sum1 = 0.f;
#pragma unroll
        for (int nt = 0; nt < 8; nt++) {
            float p00 = exp2f(sc[nt][0] - mn0);
            float p01 = exp2f(sc[nt][1] - mn0);
            float p10 = exp2f(sc[nt][2] - mn1);
            float p11 = exp2f(sc[nt][3] - mn1);
            sum0 += p00 + p01;
            sum1 += p10 + p11;
            *(__half2*)&PS(w16 + g,     nt * 8 + 2 * t) = __floats2half2_rn(p00, p01);
            *(__half2*)&PS(w16 + g + 8, nt * 8 + 2 * t) = __floats2half2_rn(p10, p11);
        }
        sum0 += __shfl_xor_sync(0xffffffffu, sum0, 1);
        sum0 += __shfl_xor_sync(0xffffffffu, sum0, 2);
        sum1 += __shfl_xor_sync(0xffffffffu, sum1, 1);
        sum1 += __shfl_xor_sync(0xffffffffu, sum1, 2);
        l0 = l0 * corr0 + sum0;
        l1 = l1 * corr1 + sum1;

#pragma unroll
        for (int d = 0; d < 8; d++) {
            o[d][0] *= corr0; o[d][1] *= corr0;
            o[d][2] *= corr1; o[d][3] *= corr1;
        }
        __syncwarp();

        // O[16x64] += P[16x64] @ V[64x64]
#pragma unroll
        for (int kk = 0; kk < 64; kk += 16) {
            uint32_t a[4];
            ldsm4(a, smem_u32(&PS(w16 + (lane & 15), kk + 8 * (lane >> 4))));
#pragma unroll
            for (int dt = 0; dt < 8; dt++) {
                uint32_t bf[2];
                ldsm2t(bf, smem_u32(&VS(s, kk + (lane & 15), dt * 8)));
                MMA_F16(o[dt], a, bf);
            }
        }
    }

    float inv0 = 1.f / l0, inv1 = 1.f / l1;
    const int r0 = qt * 128 + w16 + g;
#pragma unroll
    for (int dt = 0; dt < 8; dt++) {
        int col = h * HDIM + dt * 8 + 2 * t;
        *(__half2*)&g_ctx[((size_t)b * SEQ + r0) * HID + col] =
            __floats2half2_rn(o[dt][0] * inv0, o[dt][1] * inv0);
        *(__half2*)&g_ctx[((size_t)b * SEQ + r0 + 8) * HID + col] =
            __floats2half2_rn(o[dt][2] * inv1, o[dt][3] * inv1);
    }
#undef QS
#undef KS
#undef VS
#undef PS
}

// ----------------------------------------------------------------------------
extern "C" void kernel_launch(void* const* d_in, const int* in_sizes, int n_in,
                              void* d_out, int out_size)
{
    const float* hs = (const float*)d_in[0];
    const float* Wq = (const float*)d_in[1];
    const float* bq = (const float*)d_in[2];
    const float* Wk = (const float*)d_in[3];
    const float* bk = (const float*)d_in[4];
    const float* Wv = (const float*)d_in[5];
    const float* bv = (const float*)d_in[6];
    const float* Wd = (const float*)d_in[7];
    const float* bd = (const float*)d_in[8];

    cudaFuncSetAttribute(h_gemm<0>, cudaFuncAttributeMaxDynamicSharedMemorySize, GEMM_SMEM);
    cudaFuncSetAttribute(h_gemm<1>, cudaFuncAttributeMaxDynamicSharedMemorySize, GEMM_SMEM);
    cudaFuncSetAttribute(attn_kernel, cudaFuncAttributeMaxDynamicSharedMemorySize, ATTN_SMEM);

    const int n4_hs = MROWS * HID / 4;
    round_copy_hs<<<(n4_hs + 255) / 256, 256>>>(hs, n4_hs);            // launch 0
    wt_copy_all<<<dim3(HID / 32, HID / 32, 4), 256>>>(Wq, Wk, Wv, Wd); // launch 1

    const float qscale = 0.125f * 1.44269504088896f;   // 1/sqrt(D) * log2(e)
    dim3 gemmGrid(HID / 256, MROWS / 128);   // (4, 128)
    h_gemm<1><<<gemmGrid, 256, GEMM_SMEM>>>(bq, nullptr, 0, qscale);   // 2
    h_gemm<1><<<gemmGrid, 256, GEMM_SMEM>>>(bk, nullptr, 1, 1.f);      // 3
    h_gemm<1><<<gemmGrid, 256, GEMM_SMEM>>>(bv, nullptr, 2, 1.f);      // 4

    attn_kernel<<<dim3(SEQ / 128, HEADS, BATCH), 256, ATTN_SMEM>>>();  // 5 (ncu -s 5)

    h_gemm<0><<<gemmGrid, 256, GEMM_SMEM>>>(bd, (float*)d_out, 3, 1.f);
}

// round 11
// speedup vs baseline: 1.2705x; 1.2705x over previous
#include <cuda_runtime.h>
#include <cuda_fp16.h>
#include <cstdint>

// ============================================================================
// ViTMAE attention block: B=16, S=1024, HID=1024, HEADS=16, D=64, fp32 I/O.
// fp16 tensor cores (mma.m16n8k16, fp32 accum) + ldmatrix everywhere.
//   pre: x -> fp16 copy;  W* -> fp16 TRANSPOSED copies (one fused launch)
//   q/k/v = x@W + b  (ONE fused launch, 3-stage cp.async, BK=64, 2 CTA/SM)
//   ctx = softmax(q k^T) v  (fp16 flash attention, Bc=64, fp32 softmax)
//   out = ctx@Wd + bd  (fp32 output)
// ============================================================================

#define BATCH   16
#define SEQ     1024
#define HID     1024
#define HEADS   16
#define HDIM    64
#define MROWS   (BATCH * SEQ)   // 16384

__device__ __half g_q[(size_t)BATCH * HEADS * SEQ * HDIM];
__device__ __half g_k[(size_t)BATCH * HEADS * SEQ * HDIM];
__device__ __half g_v[(size_t)BATCH * HEADS * SEQ * HDIM];
__device__ __half g_ctx[(size_t)MROWS * HID];
__device__ __half g_hs[(size_t)MROWS * HID];
__device__ __half g_wq[(size_t)HID * HID];   // transposed: [n][k]
__device__ __half g_wk[(size_t)HID * HID];
__device__ __half g_wv[(size_t)HID * HID];
__device__ __half g_wd[(size_t)HID * HID];

__device__ __forceinline__ void cp16(void* smem, const void* gmem) {
    uint32_t s = (uint32_t)__cvta_generic_to_shared(smem);
    asm volatile("cp.async.cg.shared.global [%0], [%1], 16;" :: "r"(s), "l"(gmem));
}
#define CP_COMMIT() asm volatile("cp.async.commit_group;")
#define CP_WAIT(n)  asm volatile("cp.async.wait_group %0;" :: "n"(n))

__device__ __forceinline__ uint32_t smem_u32(const void* p) {
    return (uint32_t)__cvta_generic_to_shared(p);
}
__device__ __forceinline__ void ldsm4(uint32_t* r, uint32_t addr) {
    asm volatile("ldmatrix.sync.aligned.m8n8.x4.shared.b16 {%0,%1,%2,%3}, [%4];"
        : "=r"(r[0]), "=r"(r[1]), "=r"(r[2]), "=r"(r[3]) : "r"(addr));
}
__device__ __forceinline__ void ldsm2t(uint32_t* r, uint32_t addr) {
    asm volatile("ldmatrix.sync.aligned.m8n8.x2.trans.shared.b16 {%0,%1}, [%2];"
        : "=r"(r[0]), "=r"(r[1]) : "r"(addr));
}

#define MMA_F16(d, a, b)                                                      \
    asm volatile(                                                             \
        "mma.sync.aligned.m16n8k16.row.col.f32.f16.f16.f32 "                  \
        "{%0,%1,%2,%3}, {%4,%5,%6,%7}, {%8,%9}, {%0,%1,%2,%3};"               \
        : "+f"(d[0]), "+f"(d[1]), "+f"(d[2]), "+f"(d[3])                      \
        : "r"(a[0]), "r"(a[1]), "r"(a[2]), "r"(a[3]), "r"(b[0]), "r"(b[1]))

// ----------------------------------------------------------------------------
// pre-passes: fp32 -> fp16
// ----------------------------------------------------------------------------
__global__ __launch_bounds__(256) void round_copy_hs(const float* __restrict__ src, int n4)
{
    int i = blockIdx.x * blockDim.x + threadIdx.x;
    if (i < n4) {
        float4 v = ((const float4*)src)[i];
        ((__half2*)g_hs)[2 * i + 0] = __floats2half2_rn(v.x, v.y);
        ((__half2*)g_hs)[2 * i + 1] = __floats2half2_rn(v.z, v.w);
    }
}

// all four transposed fp16 weight copies in ONE launch (blockIdx.z selects)
__global__ __launch_bounds__(256) void wt_copy_all(
    const float* __restrict__ s0, const float* __restrict__ s1,
    const float* __restrict__ s2, const float* __restrict__ s3)
{
    __shared__ float tile[32][33];
    int which = blockIdx.z;
    const float* src = which == 0 ? s0 : which == 1 ? s1 : which == 2 ? s2 : s3;
    __half* dst = which == 0 ? g_wq : which == 1 ? g_wk :
                  which == 2 ? g_wv : g_wd;
    int tx = threadIdx.x & 31, ty = threadIdx.x >> 5;   // 32 x 8
    int x0 = blockIdx.x * 32, y0 = blockIdx.y * 32;
#pragma unroll
    for (int i = 0; i < 32; i += 8)
        tile[ty + i][tx] = src[(size_t)(y0 + ty + i) * HID + x0 + tx];
    __syncthreads();
#pragma unroll
    for (int i = 0; i < 32; i += 8)
        dst[(size_t)(x0 + ty + i) * HID + y0 + tx] = __float2half_rn(tile[tx][ty + i]);
}

// ----------------------------------------------------------------------------
// fp16 GEMM: BM=128, BN=128, BK=64, 3-stage cp.async, 256 threads (2x4 warps),
// warp tile 64x32. __launch_bounds__(256,2) -> regs<=128 -> 2 CTAs/SM.
// MODE 1: fused QKV — blockIdx.z = which (0/1/2); A=g_hs; out scattered
//         [B,H,S,D] as fp16, q scaled by qscale.
// MODE 0: A=g_ctx, Wt=g_wd, out fp32 row-major (+bias bq arg).
// smem: 3 stages x 2 tiles x 128x72 halves = 110592 B (2 CTAs = 221 KB).
// ----------------------------------------------------------------------------
#define GEMM_SMEM (3 * 2 * 128 * 72 * 2)

template <int MODE>
__global__ __launch_bounds__(256, 2) void h_gemm(
    const float* __restrict__ bq, const float* __restrict__ bk,
    const float* __restrict__ bv, float* __restrict__ outArg, float qscale)
{
    extern __shared__ __half smg[];
#define AS(s, r, c) smg[(s) * 18432 + (r) * 72 + (c)]
#define BS(s, r, c) smg[(s) * 18432 + 9216 + (r) * 72 + (c)]

    const int which = (MODE == 1) ? (int)blockIdx.z : 3;
    const __half* __restrict__ A  = (MODE == 0) ? g_ctx : g_hs;
    const __half* __restrict__ Wt = which == 0 ? g_wq : which == 1 ? g_wk :
                                    which == 2 ? g_wv : g_wd;
    const float* __restrict__ bias = (MODE == 0) ? bq :
                                     (which == 0 ? bq : which == 1 ? bk : bv);
    const float osc = (MODE == 1 && which == 0) ? qscale : 1.f;
    float* outF = outArg;
    __half* outH = (which == 0) ? g_q : (which == 1) ? g_k : g_v;

    const int tid = threadIdx.x;
    const int lane = tid & 31, warp = tid >> 5;
    const int wm = warp >> 2, wn = warp & 3;
    const int g = lane >> 2, t = lane & 3;
    const int row0 = blockIdx.y * 128;
    const int col0 = blockIdx.x * 128;

    float acc[4][4][4];
#pragma unroll
    for (int mt = 0; mt < 4; mt++)
#pragma unroll
        for (int nt = 0; nt < 4; nt++)
#pragma unroll
            for (int i = 0; i < 4; i++) acc[mt][nt][i] = 0.f;

    // BK=64 -> 8 chunks of 8 halves per row; A,B: 128 rows x 8 = 1024 chunks each
    auto stage = [&](int s, int k0) {
#pragma unroll
        for (int j = 0; j < 4; j++) {
            int cid = tid + j * 256;
            int r = cid >> 3, q = cid & 7;
            cp16(&AS(s, r, q * 8), &A [(size_t)(row0 + r) * HID + k0 + q * 8]);
            cp16(&BS(s, r, q * 8), &Wt[(size_t)(col0 + r) * HID + k0 + q * 8]);
        }
    };

    const int NIT = HID / 64;   // 16
    stage(0, 0);   CP_COMMIT();
    stage(1, 64);  CP_COMMIT();

    for (int it = 0; it < NIT; it++) {
        if (it + 1 < NIT) { CP_WAIT(1); } else { CP_WAIT(0); }
        __syncthreads();
        if (it + 2 < NIT) { stage((it + 2) % 3, (it + 2) * 64); CP_COMMIT(); }

        const int s = it % 3;
#pragma unroll
        for (int ks = 0; ks < 64; ks += 16) {
            uint32_t a[4][4], b[2][4];
#pragma unroll
            for (int mt = 0; mt < 4; mt++)
                ldsm4(a[mt], smem_u32(&AS(s, wm * 64 + mt * 16 + (lane & 15),
                                          ks + 8 * (lane >> 4))));
#pragma unroll
            for (int nt16 = 0; nt16 < 2; nt16++)
                ldsm4(b[nt16], smem_u32(&BS(s, wn * 32 + nt16 * 16 + (lane & 15),
                                            ks + 8 * (lane >> 4))));
#pragma unroll
            for (int mt = 0; mt < 4; mt++)
#pragma unroll
                for (int nt16 = 0; nt16 < 2; nt16++) {
                    uint32_t b0[2] = { b[nt16][0], b[nt16][2] };
                    uint32_t b1[2] = { b[nt16][1], b[nt16][3] };
                    MMA_F16(acc[mt][nt16 * 2 + 0], a[mt], b0);
                    MMA_F16(acc[mt][nt16 * 2 + 1], a[mt], b1);
                }
        }
    }

#pragma unroll
    for (int mt = 0; mt < 4; mt++) {
#pragma unroll
        for (int nt = 0; nt < 4; nt++) {
            int n = col0 + wn * 32 + nt * 8 + 2 * t;
            float b0 = bias[n], b1 = bias[n + 1];
#pragma unroll
            for (int hf = 0; hf < 2; hf++) {
                int m = row0 + wm * 64 + mt * 16 + g + hf * 8;
                float vx = acc[mt][nt][hf * 2 + 0] + b0;
                float vy = acc[mt][nt][hf * 2 + 1] + b1;
                if (MODE == 0) {
                    *(float2*)&outF[(size_t)m * HID + n] = make_float2(vx, vy);
                } else {
                    __half2 hv = __floats2half2_rn(vx * osc, vy * osc);
                    int bb = m >> 10, sq = m & 1023;
                    int h = n >> 6, d = n & 63;
                    *(__half2*)&outH[(((size_t)bb * HEADS + h) * SEQ + sq) * HDIM + d] = hv;
                }
            }
        }
    }
#undef AS
#undef BS
}

// ----------------------------------------------------------------------------
// fp16 flash attention, Bc=64, 3-stage cp.async K/V pipeline + ldmatrix.
// Grid (8 qtiles, 16 h, 16 b), 256 threads (8 warps, 16 q-rows each).
// Br=128, Bc=64, D=64. q pre-scaled by 0.125*log2e. fp32 softmax/accum.
// smem halves: Q 128x72 | K 3x64x72 | V 3x64x72 | P 128x72 = 92160 B.
// ----------------------------------------------------------------------------
#define ATTN_SMEM ((128 * 72 + 3 * 64 * 72 + 3 * 64 * 72 + 128 * 72) * 2)

__global__ __launch_bounds__(256, 2) void attn_kernel()
{
    extern __shared__ __half sma[];
#define QS(r, c)    sma[(r) * 72 + (c)]
#define KS(s, r, c) sma[9216  + (s) * 4608 + (r) * 72 + (c)]
#define VS(s, r, c) sma[23040 + (s) * 4608 + (r) * 72 + (c)]
#define PS(r, c)    sma[36864 + (r) * 72 + (c)]

    const int tid = threadIdx.x;
    const int lane = tid & 31, warp = tid >> 5;
    const int g = lane >> 2, t = lane & 3;
    const int w16 = warp * 16;
    const int qt = blockIdx.x, h = blockIdx.y, b = blockIdx.z;
    const size_t bh = (size_t)b * HEADS + h;
    const __half* __restrict__ qb = g_q + (bh * SEQ + qt * 128) * HDIM;
    const __half* __restrict__ kb = g_k + bh * SEQ * HDIM;
    const __half* __restrict__ vb = g_v + bh * SEQ * HDIM;

    // D=64 -> 8 chunks of 8 halves per row.
    auto stageKV = [&](int s, int kc) {
        // 64 rows x 8 chunks = 512 chunks each for K and V; 2 per thread.
#pragma unroll
        for (int j = 0; j < 2; j++) {
            int i = tid + j * 256;
            int r = i >> 3, c = (i & 7) * 8;
            cp16(&KS(s, r, c), &kb[(size_t)(kc + r) * HDIM + c]);
            cp16(&VS(s, r, c), &vb[(size_t)(kc + r) * HDIM + c]);
        }
    };

    // Q: 128 rows x 8 chunks = 1024 chunks.
#pragma unroll
    for (int j = 0; j < 4; j++) {
        int i = tid + j * 256;
        int r = i >> 3, c = (i & 7) * 8;
        cp16(&QS(r, c), &qb[(size_t)r * HDIM + c]);
    }
    stageKV(0, 0);  CP_COMMIT();
    stageKV(1, 64); CP_COMMIT();

    float m0 = -1e30f, m1 = -1e30f, l0 = 0.f, l1 = 0.f;
    float o[8][4];
#pragma unroll
    for (int d = 0; d < 8; d++)
#pragma unroll
        for (int i = 0; i < 4; i++) o[d][i] = 0.f;

    const int NKV = SEQ / 64;   // 16
    for (int it = 0; it < NKV; it++) {
        if (it + 1 < NKV) { CP_WAIT(1); } else { CP_WAIT(0); }
        __syncthreads();
        if (it + 2 < NKV) { stageKV((it + 2) % 3, (it + 2) * 64); CP_COMMIT(); }

        const int s = it % 3;

        // S[16x64] = Q_warp @ K^T
        float sc[8][4];
#pragma unroll
        for (int nt = 0; nt < 8; nt++)
#pragma unroll
            for (int i = 0; i < 4; i++) sc[nt][i] = 0.f;

#pragma unroll
        for (int ks = 0; ks < 64; ks += 16) {
            uint32_t a[4], kf[4][4];
            ldsm4(a, smem_u32(&QS(w16 + (lane & 15), ks + 8 * (lane >> 4))));
#pragma unroll
            for (int nt16 = 0; nt16 < 4; nt16++)
                ldsm4(kf[nt16], smem_u32(&KS(s, nt16 * 16 + (lane & 15),
                                             ks + 8 * (lane >> 4))));
#pragma unroll
            for (int nt16 = 0; nt16 < 4; nt16++) {
                uint32_t b0[2] = { kf[nt16][0], kf[nt16][2] };
                uint32_t b1[2] = { kf[nt16][1], kf[nt16][3] };
                MMA_F16(sc[nt16 * 2 + 0], a, b0);
                MMA_F16(sc[nt16 * 2 + 1], a, b1);
            }
        }

        // online softmax (rows g, g+8)
        float mx0 = -1e30f, mx1 = -1e30f;
#pragma unroll
        for (int nt = 0; nt < 8; nt++) {
            mx0 = fmaxf(mx0, fmaxf(sc[nt][0], sc[nt][1]));
            mx1 = fmaxf(mx1, fmaxf(sc[nt][2], sc[nt][3]));
        }
        mx0 = fmaxf(mx0, __shfl_xor_sync(0xffffffffu, mx0, 1));
        mx0 = fmaxf(mx0, __shfl_xor_sync(0xffffffffu, mx0, 2));
        mx1 = fmaxf(mx1, __shfl_xor_sync(0xffffffffu, mx1, 1));
        mx1 = fmaxf(mx1, __shfl_xor_sync(0xffffffffu, mx1, 2));

        float mn0 = fmaxf(m0, mx0), mn1 = fmaxf(m1, mx1);
        float corr0 = exp2f(m0 - mn0), corr1 = exp2f(m1 - mn1);
        m0 = mn0; m1 = mn1;

        float sum0 = 0.f, sum1 = 0.f;
#pragma unroll
        for (int nt = 0; nt < 8; nt++) {
            float p00 = exp2f(sc[nt][0] - mn0);
            float p01 = exp2f(sc[nt][1] - mn0);
            float p10 = exp2f(sc[nt][2] - mn1);
            float p11 = exp2f(sc[nt][3] - mn1);
            sum0 += p00 + p01;
            sum1 += p10 + p11;
            *(__half2*)&PS(w16 + g,     nt * 8 + 2 * t) = __floats2half2_rn(p00, p01);
            *(__half2*)&PS(w16 + g + 8, nt * 8 + 2 * t) = __floats2half2_rn(p10, p11);
        }
        sum0 += __shfl_xor_sync(0xffffffffu, sum0, 1);
        sum0 += __shfl_xor_sync(0xffffffffu, sum0, 2);
        sum1 += __shfl_xor_sync(0xffffffffu, sum1, 1);
        sum1 += __shfl_xor_sync(0xffffffffu, sum1, 2);
        l0 = l0 * corr0 + sum0;
        l1 = l1 * corr1 + sum1;

#pragma unroll
        for (int d = 0; d < 8; d++) {
            o[d][0] *= corr0; o[d][1] *= corr0;
            o[d][2] *= corr1; o[d][3] *= corr1;
        }
        __syncwarp();

        // O[16x64] += P[16x64] @ V[64x64]
#pragma unroll
        for (int kk = 0; kk < 64; kk += 16) {
            uint32_t a[4];
            ldsm4(a, smem_u32(&PS(w16 + (lane & 15), kk + 8 * (lane >> 4))));
#pragma unroll
            for (int dt = 0; dt < 8; dt++) {
                uint32_t bf[2];
                ldsm2t(bf, smem_u32(&VS(s, kk + (lane & 15), dt * 8)));
                MMA_F16(o[dt], a, bf);
            }
        }
    }

    float inv0 = 1.f / l0, inv1 = 1.f / l1;
    const int r0 = qt * 128 + w16 + g;
#pragma unroll
    for (int dt = 0; dt < 8; dt++) {
        int col = h * HDIM + dt * 8 + 2 * t;
        *(__half2*)&g_ctx[((size_t)b * SEQ + r0) * HID + col] =
            __floats2half2_rn(o[dt][0] * inv0, o[dt][1] * inv0);
        *(__half2*)&g_ctx[((size_t)b * SEQ + r0 + 8) * HID + col] =
            __floats2half2_rn(o[dt][2] * inv1, o[dt][3] * inv1);
    }
#undef QS
#undef KS
#undef VS
#undef PS
}

// ----------------------------------------------------------------------------
extern "C" void kernel_launch(void* const* d_in, const int* in_sizes, int n_in,
                              void* d_out, int out_size)
{
    const float* hs = (const float*)d_in[0];
    const float* Wq = (const float*)d_in[1];
    const float* bq = (const float*)d_in[2];
    const float* Wk = (const float*)d_in[3];
    const float* bk = (const float*)d_in[4];
    const float* Wv = (const float*)d_in[5];
    const float* bv = (const float*)d_in[6];
    const float* Wd = (const float*)d_in[7];
    const float* bd = (const float*)d_in[8];

    cudaFuncSetAttribute(h_gemm<0>, cudaFuncAttributeMaxDynamicSharedMemorySize, GEMM_SMEM);
    cudaFuncSetAttribute(h_gemm<1>, cudaFuncAttributeMaxDynamicSharedMemorySize, GEMM_SMEM);
    cudaFuncSetAttribute(attn_kernel, cudaFuncAttributeMaxDynamicSharedMemorySize, ATTN_SMEM);

    const int n4_hs = MROWS * HID / 4;
    round_copy_hs<<<(n4_hs + 255) / 256, 256>>>(hs, n4_hs);            // launch 0
    wt_copy_all<<<dim3(HID / 32, HID / 32, 4), 256>>>(Wq, Wk, Wv, Wd); // launch 1

    const float qscale = 0.125f * 1.44269504088896f;   // 1/sqrt(D) * log2(e)

    // fused QKV: grid (8, 128, 3)
    h_gemm<1><<<dim3(HID / 128, MROWS / 128, 3), 256, GEMM_SMEM>>>(
        bq, bk, bv, nullptr, qscale);                                  // launch 2

    attn_kernel<<<dim3(SEQ / 128, HEADS, BATCH), 256, ATTN_SMEM>>>();  // launch 3

    h_gemm<0><<<dim3(HID / 128, MROWS / 128, 1), 256, GEMM_SMEM>>>(
        bd, nullptr, nullptr, (float*)d_out, 1.f);                     // launch 4
}

// round 12
// speedup vs baseline: 1.3100x; 1.0311x over previous
#include <cuda_runtime.h>
#include <cuda_fp16.h>
#include <cstdint>

// ============================================================================
// ViTMAE attention block: B=16, S=1024, HID=1024, HEADS=16, D=64, fp32 I/O.
// fp16 tensor cores (mma.m16n8k16, fp32 accum) + ldmatrix everywhere.
//   pre: x -> fp16 copy;  W* -> fp16 TRANSPOSED copies (one fused launch)
//   q/k/v = x@W + b  (ONE fused launch, 3-stage cp.async, BK=64, 2 CTA/SM)
//   ctx = softmax(q k^T) v  (register-pipeline flash attention: P stays in
//         registers via C->A fragment layout identity; Q frags hoisted)
//   out = ctx@Wd + bd  (fp32 output)
// ============================================================================

#define BATCH   16
#define SEQ     1024
#define HID     1024
#define HEADS   16
#define HDIM    64
#define MROWS   (BATCH * SEQ)   // 16384

__device__ __half g_q[(size_t)BATCH * HEADS * SEQ * HDIM];
__device__ __half g_k[(size_t)BATCH * HEADS * SEQ * HDIM];
__device__ __half g_v[(size_t)BATCH * HEADS * SEQ * HDIM];
__device__ __half g_ctx[(size_t)MROWS * HID];
__device__ __half g_hs[(size_t)MROWS * HID];
__device__ __half g_wq[(size_t)HID * HID];   // transposed: [n][k]
__device__ __half g_wk[(size_t)HID * HID];
__device__ __half g_wv[(size_t)HID * HID];
__device__ __half g_wd[(size_t)HID * HID];

__device__ __forceinline__ void cp16(void* smem, const void* gmem) {
    uint32_t s = (uint32_t)__cvta_generic_to_shared(smem);
    asm volatile("cp.async.cg.shared.global [%0], [%1], 16;" :: "r"(s), "l"(gmem));
}
#define CP_COMMIT() asm volatile("cp.async.commit_group;")
#define CP_WAIT(n)  asm volatile("cp.async.wait_group %0;" :: "n"(n))

__device__ __forceinline__ uint32_t smem_u32(const void* p) {
    return (uint32_t)__cvta_generic_to_shared(p);
}
__device__ __forceinline__ void ldsm4(uint32_t* r, uint32_t addr) {
    asm volatile("ldmatrix.sync.aligned.m8n8.x4.shared.b16 {%0,%1,%2,%3}, [%4];"
        : "=r"(r[0]), "=r"(r[1]), "=r"(r[2]), "=r"(r[3]) : "r"(addr));
}
__device__ __forceinline__ void ldsm4t(uint32_t* r, uint32_t addr) {
    asm volatile("ldmatrix.sync.aligned.m8n8.x4.trans.shared.b16 {%0,%1,%2,%3}, [%4];"
        : "=r"(r[0]), "=r"(r[1]), "=r"(r[2]), "=r"(r[3]) : "r"(addr));
}

#define MMA_F16(d, a, b)                                                      \
    asm volatile(                                                             \
        "mma.sync.aligned.m16n8k16.row.col.f32.f16.f16.f32 "                  \
        "{%0,%1,%2,%3}, {%4,%5,%6,%7}, {%8,%9}, {%0,%1,%2,%3};"               \
        : "+f"(d[0]), "+f"(d[1]), "+f"(d[2]), "+f"(d[3])                      \
        : "r"(a[0]), "r"(a[1]), "r"(a[2]), "r"(a[3]), "r"(b[0]), "r"(b[1]))

// ----------------------------------------------------------------------------
// pre-passes: fp32 -> fp16
// ----------------------------------------------------------------------------
__global__ __launch_bounds__(256) void round_copy_hs(const float* __restrict__ src, int n4)
{
    int i = blockIdx.x * blockDim.x + threadIdx.x;
    if (i < n4) {
        float4 v = ((const float4*)src)[i];
        ((__half2*)g_hs)[2 * i + 0] = __floats2half2_rn(v.x, v.y);
        ((__half2*)g_hs)[2 * i + 1] = __floats2half2_rn(v.z, v.w);
    }
}

// all four transposed fp16 weight copies in ONE launch (blockIdx.z selects)
__global__ __launch_bounds__(256) void wt_copy_all(
    const float* __restrict__ s0, const float* __restrict__ s1,
    const float* __restrict__ s2, const float* __restrict__ s3)
{
    __shared__ float tile[32][33];
    int which = blockIdx.z;
    const float* src = which == 0 ? s0 : which == 1 ? s1 : which == 2 ? s2 : s3;
    __half* dst = which == 0 ? g_wq : which == 1 ? g_wk :
                  which == 2 ? g_wv : g_wd;
    int tx = threadIdx.x & 31, ty = threadIdx.x >> 5;   // 32 x 8
    int x0 = blockIdx.x * 32, y0 = blockIdx.y * 32;
#pragma unroll
    for (int i = 0; i < 32; i += 8)
        tile[ty + i][tx] = src[(size_t)(y0 + ty + i) * HID + x0 + tx];
    __syncthreads();
#pragma unroll
    for (int i = 0; i < 32; i += 8)
        dst[(size_t)(x0 + ty + i) * HID + y0 + tx] = __float2half_rn(tile[tx][ty + i]);
}

// ----------------------------------------------------------------------------
// fp16 GEMM: BM=128, BN=128, BK=64, 3-stage cp.async, 256 threads (2x4 warps),
// warp tile 64x32. __launch_bounds__(256,2) -> regs<=128 -> 2 CTAs/SM.
// MODE 1: fused QKV — blockIdx.z = which (0/1/2); A=g_hs; out scattered
//         [B,H,S,D] as fp16, q scaled by qscale.
// MODE 0: A=g_ctx, Wt=g_wd, out fp32 row-major (+bias bq arg).
// smem: 3 stages x 2 tiles x 128x72 halves = 110592 B (2 CTAs = 221 KB).
// ----------------------------------------------------------------------------
#define GEMM_SMEM (3 * 2 * 128 * 72 * 2)

template <int MODE>
__global__ __launch_bounds__(256, 2) void h_gemm(
    const float* __restrict__ bq, const float* __restrict__ bk,
    const float* __restrict__ bv, float* __restrict__ outArg, float qscale)
{
    extern __shared__ __half smg[];
#define AS(s, r, c) smg[(s) * 18432 + (r) * 72 + (c)]
#define BS(s, r, c) smg[(s) * 18432 + 9216 + (r) * 72 + (c)]

    const int which = (MODE == 1) ? (int)blockIdx.z : 3;
    const __half* __restrict__ A  = (MODE == 0) ? g_ctx : g_hs;
    const __half* __restrict__ Wt = which == 0 ? g_wq : which == 1 ? g_wk :
                                    which == 2 ? g_wv : g_wd;
    const float* __restrict__ bias = (MODE == 0) ? bq :
                                     (which == 0 ? bq : which == 1 ? bk : bv);
    const float osc = (MODE == 1 && which == 0) ? qscale : 1.f;
    float* outF = outArg;
    __half* outH = (which == 0) ? g_q : (which == 1) ? g_k : g_v;

    const int tid = threadIdx.x;
    const int lane = tid & 31, warp = tid >> 5;
    const int wm = warp >> 2, wn = warp & 3;
    const int g = lane >> 2, t = lane & 3;
    const int row0 = blockIdx.y * 128;
    const int col0 = blockIdx.x * 128;

    float acc[4][4][4];
#pragma unroll
    for (int mt = 0; mt < 4; mt++)
#pragma unroll
        for (int nt = 0; nt < 4; nt++)
#pragma unroll
            for (int i = 0; i < 4; i++) acc[mt][nt][i] = 0.f;

    // BK=64 -> 8 chunks of 8 halves per row; A,B: 128 rows x 8 = 1024 chunks each
    auto stage = [&](int s, int k0) {
#pragma unroll
        for (int j = 0; j < 4; j++) {
            int cid = tid + j * 256;
            int r = cid >> 3, q = cid & 7;
            cp16(&AS(s, r, q * 8), &A [(size_t)(row0 + r) * HID + k0 + q * 8]);
            cp16(&BS(s, r, q * 8), &Wt[(size_t)(col0 + r) * HID + k0 + q * 8]);
        }
    };

    const int NIT = HID / 64;   // 16
    stage(0, 0);   CP_COMMIT();
    stage(1, 64);  CP_COMMIT();

    for (int it = 0; it < NIT; it++) {
        if (it + 1 < NIT) { CP_WAIT(1); } else { CP_WAIT(0); }
        __syncthreads();
        if (it + 2 < NIT) { stage((it + 2) % 3, (it + 2) * 64); CP_COMMIT(); }

        const int s = it % 3;
#pragma unroll
        for (int ks = 0; ks < 64; ks += 16) {
            uint32_t a[4][4], b[2][4];
#pragma unroll
            for (int mt = 0; mt < 4; mt++)
                ldsm4(a[mt], smem_u32(&AS(s, wm * 64 + mt * 16 + (lane & 15),
                                          ks + 8 * (lane >> 4))));
#pragma unroll
            for (int nt16 = 0; nt16 < 2; nt16++)
                ldsm4(b[nt16], smem_u32(&BS(s, wn * 32 + nt16 * 16 + (lane & 15),
                                            ks + 8 * (lane >> 4))));
#pragma unroll
            for (int mt = 0; mt < 4; mt++)
#pragma unroll
                for (int nt16 = 0; nt16 < 2; nt16++) {
                    uint32_t b0[2] = { b[nt16][0], b[nt16][2] };
                    uint32_t b1[2] = { b[nt16][1], b[nt16][3] };
                    MMA_F16(acc[mt][nt16 * 2 + 0], a[mt], b0);
                    MMA_F16(acc[mt][nt16 * 2 + 1], a[mt], b1);
                }
        }
    }

#pragma unroll
    for (int mt = 0; mt < 4; mt++) {
#pragma unroll
        for (int nt = 0; nt < 4; nt++) {
            int n = col0 + wn * 32 + nt * 8 + 2 * t;
            float b0 = bias[n], b1 = bias[n + 1];
#pragma unroll
            for (int hf = 0; hf < 2; hf++) {
                int m = row0 + wm * 64 + mt * 16 + g + hf * 8;
                float vx = acc[mt][nt][hf * 2 + 0] + b0;
                float vy = acc[mt][nt][hf * 2 + 1] + b1;
                if (MODE == 0) {
                    *(float2*)&outF[(size_t)m * HID + n] = make_float2(vx, vy);
                } else {
                    __half2 hv = __floats2half2_rn(vx * osc, vy * osc);
                    int bb = m >> 10, sq = m & 1023;
                    int h = n >> 6, d = n & 63;
                    *(__half2*)&outH[(((size_t)bb * HEADS + h) * SEQ + sq) * HDIM + d] = hv;
                }
            }
        }
    }
#undef AS
#undef BS
}

// ----------------------------------------------------------------------------
// fp16 flash attention, register pipeline. Bc=64, 3-stage cp.async K/V.
// Grid (8 qtiles, 16 h, 16 b), 256 threads (8 warps, 16 q-rows each).
// Br=128, Bc=64, D=64. q pre-scaled by 0.125*log2e. fp32 softmax/accum.
// P never touches smem: C-fragment(m16n8 f32) layout == A-fragment(f16)
// layout, so exp2 results are packed directly into MMA A operands.
// smem halves: Q 128x72 | K 3x64x72 | V 3x64x72 = 73728 B.
// ----------------------------------------------------------------------------
#define ATTN_SMEM ((128 * 72 + 3 * 64 * 72 + 3 * 64 * 72) * 2)

__global__ __launch_bounds__(256, 2) void attn_kernel()
{
    extern __shared__ __half sma[];
#define QS(r, c)    sma[(r) * 72 + (c)]
#define KS(s, r, c) sma[9216  + (s) * 4608 + (r) * 72 + (c)]
#define VS(s, r, c) sma[23040 + (s) * 4608 + (r) * 72 + (c)]

    const int tid = threadIdx.x;
    const int lane = tid & 31, warp = tid >> 5;
    const int g = lane >> 2, t = lane & 3;
    const int w16 = warp * 16;
    const int qt = blockIdx.x, h = blockIdx.y, b = blockIdx.z;
    const size_t bh = (size_t)b * HEADS + h;
    const __half* __restrict__ qb = g_q + (bh * SEQ + qt * 128) * HDIM;
    const __half* __restrict__ kb = g_k + bh * SEQ * HDIM;
    const __half* __restrict__ vb = g_v + bh * SEQ * HDIM;

    // lane-dependent byte offsets (row stride = 144 B)
    const uint32_t loff = (uint32_t)((lane & 15) * 144 + (lane >> 4) * 16);
    const uint32_t ks_base = smem_u32(&KS(0, 0, 0));
    const uint32_t vs_base = smem_u32(&VS(0, 0, 0));

    // D=64 -> 8 chunks of 8 halves per row.
    auto stageKV = [&](int s, int kc) {
#pragma unroll
        for (int j = 0; j < 2; j++) {
            int i = tid + j * 256;
            int r = i >> 3, c = (i & 7) * 8;
            cp16(&KS(s, r, c), &kb[(size_t)(kc + r) * HDIM + c]);
            cp16(&VS(s, r, c), &vb[(size_t)(kc + r) * HDIM + c]);
        }
    };

    // Q: 128 rows x 8 chunks = 1024 chunks.
#pragma unroll
    for (int j = 0; j < 4; j++) {
        int i = tid + j * 256;
        int r = i >> 3, c = (i & 7) * 8;
        cp16(&QS(r, c), &qb[(size_t)r * HDIM + c]);
    }
    stageKV(0, 0);  CP_COMMIT();     // group 0 = Q + KV0
    stageKV(1, 64); CP_COMMIT();     // group 1 = KV1

    float m0 = -1e30f, m1 = -1e30f, l0 = 0.f, l1 = 0.f;
    float o[8][4];
#pragma unroll
    for (int d = 0; d < 8; d++)
#pragma unroll
        for (int i = 0; i < 4; i++) o[d][i] = 0.f;

    uint32_t qf[4][4];   // Q fragments, resident all kernel

    const int NKV = SEQ / 64;   // 16
    for (int it = 0; it < NKV; it++) {
        if (it + 1 < NKV) { CP_WAIT(1); } else { CP_WAIT(0); }
        __syncthreads();
        if (it == 0) {
            // Q is now resident: load its fragments once.
            uint32_t q_base = smem_u32(&QS(w16, 0));
#pragma unroll
            for (int j = 0; j < 4; j++)
                ldsm4(qf[j], q_base + loff + (uint32_t)(j * 32));
        }
        if (it + 2 < NKV) { stageKV((it + 2) % 3, (it + 2) * 64); CP_COMMIT(); }

        const uint32_t ksb = ks_base + (uint32_t)((it % 3) * 9216) + loff;
        const uint32_t vsb = vs_base + (uint32_t)((it % 3) * 9216) + loff;

        // S[16x64] = Q_warp @ K^T
        float sc[8][4];
#pragma unroll
        for (int nt = 0; nt < 8; nt++)
#pragma unroll
            for (int i = 0; i < 4; i++) sc[nt][i] = 0.f;

#pragma unroll
        for (int j = 0; j < 4; j++) {       // k16 step over D
#pragma unroll
            for (int nt16 = 0; nt16 < 4; nt16++) {
                uint32_t kf[4];
                ldsm4(kf, ksb + (uint32_t)(nt16 * 2304 + j * 32));
                uint32_t b0[2] = { kf[0], kf[2] };
                uint32_t b1[2] = { kf[1], kf[3] };
                MMA_F16(sc[nt16 * 2 + 0], qf[j], b0);
                MMA_F16(sc[nt16 * 2 + 1], qf[j], b1);
            }
        }

        // online softmax (rows g, g+8); pack P into A-fragments in registers
        float mx0 = -1e30f, mx1 = -1e30f;
#pragma unroll
        for (int nt = 0; nt < 8; nt++) {
            mx0 = fmaxf(mx0, fmaxf(sc[nt][0], sc[nt][1]));
            mx1 = fmaxf(mx1, fmaxf(sc[nt][2], sc[nt][3]));
        }
        mx0 = fmaxf(mx0, __shfl_xor_sync(0xffffffffu, mx0, 1));
        mx0 = fmaxf(mx0, __shfl_xor_sync(0xffffffffu, mx0, 2));
        mx1 = fmaxf(mx1, __shfl_xor_sync(0xffffffffu, mx1, 1));
        mx1 = fmaxf(mx1, __shfl_xor_sync(0xffffffffu, mx1, 2));

        float mn0 = fmaxf(m0, mx0), mn1 = fmaxf(m1, mx1);
        float corr0 = exp2f(m0 - mn0), corr1 = exp2f(m1 - mn1);
        m0 = mn0; m1 = mn1;

        uint32_t pa[4][4];   // A-fragments of P for the 4 k16 blocks
        float sum0 = 0.f, sum1 = 0.f;
#pragma unroll
        for (int j = 0; j < 4; j++) {
#pragma unroll
            for (int half16 = 0; half16 < 2; half16++) {
                const int nt = j * 2 + half16;
                float p00 = exp2f(sc[nt][0] - mn0);
                float p01 = exp2f(sc[nt][1] - mn0);
                float p10 = exp2f(sc[nt][2] - mn1);
                float p11 = exp2f(sc[nt][3] - mn1);
                sum0 += p00 + p01;
                sum1 += p10 + p11;
                __half2 h0 = __floats2half2_rn(p00, p01);
                __half2 h1 = __floats2half2_rn(p10, p11);
                pa[j][half16 * 2 + 0] = *(uint32_t*)&h0;   // rows g
                pa[j][half16 * 2 + 1] = *(uint32_t*)&h1;   // rows g+8
            }
        }
        sum0 += __shfl_xor_sync(0xffffffffu, sum0, 1);
        sum0 += __shfl_xor_sync(0xffffffffu, sum0, 2);
        sum1 += __shfl_xor_sync(0xffffffffu, sum1, 1);
        sum1 += __shfl_xor_sync(0xffffffffu, sum1, 2);
        l0 = l0 * corr0 + sum0;
        l1 = l1 * corr1 + sum1;

#pragma unroll
        for (int d = 0; d < 8; d++) {
            o[d][0] *= corr0; o[d][1] *= corr0;
            o[d][2] *= corr1; o[d][3] *= corr1;
        }

        // O[16x64] += P[16x64] @ V[64x64]; V via x4.trans (16 cols per load)
#pragma unroll
        for (int j = 0; j < 4; j++) {       // k16 block (64 key rows / 4)
#pragma unroll
            for (int p = 0; p < 4; p++) {   // 16-col group of D
                uint32_t vf[4];
                ldsm4t(vf, vsb + (uint32_t)(j * 16 * 144 + p * 32));
                uint32_t b0[2] = { vf[0], vf[1] };
                uint32_t b1[2] = { vf[2], vf[3] };
                MMA_F16(o[p * 2 + 0], pa[j], b0);
                MMA_F16(o[p * 2 + 1], pa[j], b1);
            }
        }
    }

    float inv0 = 1.f / l0, inv1 = 1.f / l1;
    const int r0 = qt * 128 + w16 + g;
#pragma unroll
    for (int dt = 0; dt < 8; dt++) {
        int col = h * HDIM + dt * 8 + 2 * t;
        *(__half2*)&g_ctx[((size_t)b * SEQ + r0) * HID + col] =
            __floats2half2_rn(o[dt][0] * inv0, o[dt][1] * inv0);
        *(__half2*)&g_ctx[((size_t)b * SEQ + r0 + 8) * HID + col] =
            __floats2half2_rn(o[dt][2] * inv1, o[dt][3] * inv1);
    }
#undef QS
#undef KS
#undef VS
}

// ----------------------------------------------------------------------------
extern "C" void kernel_launch(void* const* d_in, const int* in_sizes, int n_in,
                              void* d_out, int out_size)
{
    const float* hs = (const float*)d_in[0];
    const float* Wq = (const float*)d_in[1];
    const float* bq = (const float*)d_in[2];
    const float* Wk = (const float*)d_in[3];
    const float* bk = (const float*)d_in[4];
    const float* Wv = (const float*)d_in[5];
    const float* bv = (const float*)d_in[6];
    const float* Wd = (const float*)d_in[7];
    const float* bd = (const float*)d_in[8];

    cudaFuncSetAttribute(h_gemm<0>, cudaFuncAttributeMaxDynamicSharedMemorySize, GEMM_SMEM);
    cudaFuncSetAttribute(h_gemm<1>, cudaFuncAttributeMaxDynamicSharedMemorySize, GEMM_SMEM);
    cudaFuncSetAttribute(attn_kernel, cudaFuncAttributeMaxDynamicSharedMemorySize, ATTN_SMEM);

    const int n4_hs = MROWS * HID / 4;
    round_copy_hs<<<(n4_hs + 255) / 256, 256>>>(hs, n4_hs);            // launch 0
    wt_copy_all<<<dim3(HID / 32, HID / 32, 4), 256>>>(Wq, Wk, Wv, Wd); // launch 1

    const float qscale = 0.125f * 1.44269504088896f;   // 1/sqrt(D) * log2(e)

    // fused QKV: grid (8, 128, 3)
    h_gemm<1><<<dim3(HID / 128, MROWS / 128, 3), 256, GEMM_SMEM>>>(
        bq, bk, bv, nullptr, qscale);                                  // launch 2

    attn_kernel<<<dim3(SEQ / 128, HEADS, BATCH), 256, ATTN_SMEM>>>();  // launch 3

    h_gemm<0><<<dim3(HID / 128, MROWS / 128, 1), 256, GEMM_SMEM>>>(
        bd, nullptr, nullptr, (float*)d_out, 1.f);                     // launch 4
}